// round 5
// baseline (speedup 1.0000x reference)
#include <cuda_runtime.h>
#include <cuda_bf16.h>
#include <math.h>
#include <stdint.h>

#define BB    8
#define CIN   256
#define OUTC  256
#define SHAREC 8
#define GG    32
#define MID   320
#define MIDP  384
#define WOUT  288
#define P     4096

// ---------------- scratch (static device arrays; no allocation) ----------------
__device__ float g_y[(size_t)BB * MID * P];      // conv1x1 outputs [b][c][p]
__device__ float g_t[(size_t)BB * GG * P];       // weight-gen hidden
__device__ float g_w[(size_t)BB * WOUT * P];     // per-pixel kernels
__device__ float g_bias[MIDP];
__device__ float g_bn1s[MID];
__device__ float g_bn1b[MID];
__device__ float g_bn2s[GG];
__device__ float g_bn2b[GG];
__device__ __nv_bfloat16 g_whi[MIDP * CIN];      // conv weights hi/lo, [m][k]
__device__ __nv_bfloat16 g_wlo[MIDP * CIN];
__device__ __nv_bfloat16 g_xhi[(size_t)BB * P * CIN];  // x transposed: [b][p][c]
__device__ __nv_bfloat16 g_xlo[(size_t)BB * P * CIN];
__device__ __nv_bfloat16 g_c1hi[GG * MID];       // cw1 hi/lo, [g][k]
__device__ __nv_bfloat16 g_c1lo[GG * MID];

__device__ __forceinline__ uint32_t smem_u32(const void* p) {
    uint32_t a;
    asm("{ .reg .u64 t; cvta.to.shared.u64 t, %1; cvt.u32.u64 %0, t; }" : "=r"(a) : "l"(p));
    return a;
}

#define LDSM4(r0, r1, r2, r3, addr) \
    asm volatile("ldmatrix.sync.aligned.m8n8.x4.shared.b16 {%0,%1,%2,%3}, [%4];" \
        : "=r"(r0), "=r"(r1), "=r"(r2), "=r"(r3) : "r"(addr))

#define MMA_BF16(d, a, b) \
    asm volatile("mma.sync.aligned.m16n8k16.row.col.f32.bf16.bf16.f32 " \
        "{%0,%1,%2,%3}, {%4,%5,%6,%7}, {%8,%9}, {%0,%1,%2,%3};" \
        : "+f"((d)[0]), "+f"((d)[1]), "+f"((d)[2]), "+f"((d)[3]) \
        : "r"((a)[0]), "r"((a)[1]), "r"((a)[2]), "r"((a)[3]), "r"((b)[0]), "r"((b)[1]))

// ---------------- K0: pack weights + fold BN params + bf16 splits ----------------
__global__ void pack_kernel(const float* __restrict__ w1, const float* __restrict__ b1,
                            const float* __restrict__ w2, const float* __restrict__ b2,
                            const float* __restrict__ w3, const float* __restrict__ b3,
                            const float* __restrict__ bn1_g, const float* __restrict__ bn1_b,
                            const float* __restrict__ bn1_m, const float* __restrict__ bn1_v,
                            const float* __restrict__ bn2_g, const float* __restrict__ bn2_b,
                            const float* __restrict__ bn2_m, const float* __restrict__ bn2_v,
                            const float* __restrict__ cw1) {
    int c = blockIdx.x * blockDim.x + threadIdx.x;
    if (c >= MIDP) return;
    if (c >= MID) {
        for (int k = 0; k < CIN; k++) {
            g_whi[c * CIN + k] = __float2bfloat16(0.f);
            g_wlo[c * CIN + k] = __float2bfloat16(0.f);
        }
        g_bias[c] = 0.f;
        return;
    }
    const float* src;
    float bv;
    if (c < 32)      { src = w1 + (size_t)c * CIN;        bv = b1[c]; }
    else if (c < 64) { src = w2 + (size_t)(c - 32) * CIN; bv = b2[c - 32]; }
    else             { src = w3 + (size_t)(c - 64) * CIN; bv = b3[c - 64]; }
    for (int k = 0; k < CIN; k++) {
        float v = src[k];
        __nv_bfloat16 hi = __float2bfloat16(v);
        g_whi[c * CIN + k] = hi;
        g_wlo[c * CIN + k] = __float2bfloat16(v - __bfloat162float(hi));
    }
    g_bias[c] = bv;
    float s = bn1_g[c] * rsqrtf(bn1_v[c] + 1e-5f);
    g_bn1s[c] = s;
    g_bn1b[c] = bn1_b[c] - bn1_m[c] * s;
    if (c < GG) {
        float s2 = bn2_g[c] * rsqrtf(bn2_v[c] + 1e-5f);
        g_bn2s[c] = s2;
        g_bn2b[c] = bn2_b[c] - bn2_m[c] * s2;
        for (int k = 0; k < MID; k++) {
            float v = cw1[c * MID + k];
            __nv_bfloat16 hi = __float2bfloat16(v);
            g_c1hi[c * MID + k] = hi;
            g_c1lo[c * MID + k] = __float2bfloat16(v - __bfloat162float(hi));
        }
    }
}

// ---------------- K0b: transpose + split-convert x -> [b][p][c] bf16 hi/lo ----------------
__global__ __launch_bounds__(256) void xconv_kernel(const float* __restrict__ x) {
    __shared__ float tile[64][33];
    const int b  = blockIdx.z;
    const int c0 = blockIdx.y * 64;
    const int p0 = blockIdx.x * 32;
    const int tid = threadIdx.x;
#pragma unroll
    for (int e = 0; e < 8; e++) {
        int idx = tid + e * 256;
        int c = idx >> 5, j = idx & 31;
        tile[c][j] = x[((size_t)b * CIN + c0 + c) * P + p0 + j];
    }
    __syncthreads();
#pragma unroll
    for (int e = 0; e < 4; e++) {
        int idx = tid + e * 256;
        int p = idx >> 5, cp = idx & 31;
        float f0 = tile[2 * cp][p], f1 = tile[2 * cp + 1][p];
        __nv_bfloat16 h0 = __float2bfloat16(f0);
        __nv_bfloat16 h1 = __float2bfloat16(f1);
        __nv_bfloat16 l0 = __float2bfloat16(f0 - __bfloat162float(h0));
        __nv_bfloat16 l1 = __float2bfloat16(f1 - __bfloat162float(h1));
        size_t off = ((size_t)b * P + p0 + p) * CIN + c0 + 2 * cp;
        *(__nv_bfloat162*)&g_xhi[off] = __nv_bfloat162(h0, h1);
        *(__nv_bfloat162*)&g_xlo[off] = __nv_bfloat162(l0, l1);
    }
}

// ---------------- K1: conv1x1 via mma.sync split-bf16 GEMM (unchanged, proven) ----------------
#define KC 64
#define SM_AHI 0
#define SM_ALO 16384
#define SM_BHI 32768
#define SM_BLO 49152
#define SM_TOTAL 65536

__global__ __launch_bounds__(256) void conv_mma_kernel() {
    extern __shared__ char smem[];
    const uint32_t sbase = smem_u32(smem);
    const int tid = threadIdx.x;
    const int wid = tid >> 5;
    const int lid = tid & 31;
    const int b  = blockIdx.z;
    const int m0 = blockIdx.y * 128;
    const int p0 = blockIdx.x * 128;
    const int wm = wid & 3;
    const int wn = wid >> 2;

    float acc[2][8][4];
#pragma unroll
    for (int i = 0; i < 2; i++)
#pragma unroll
        for (int j = 0; j < 8; j++)
#pragma unroll
            for (int q = 0; q < 4; q++) acc[i][j][q] = 0.f;

    const int rowA[2] = { wm * 32 + (lid & 15), wm * 32 + 16 + (lid & 15) };
    const int c16A = (lid >> 4) * 16;
    int rowB[4];
#pragma unroll
    for (int nfp = 0; nfp < 4; nfp++)
        rowB[nfp] = wn * 64 + nfp * 16 + ((lid >> 4) * 8) + (lid & 7);
    const int c16B = ((lid >> 3) & 1) * 16;

    const int rowL = tid >> 3;
    const int ccL  = (tid & 7) * 16;

    for (int c = 0; c < 4; c++) {
        const int kk = c * KC;
#pragma unroll
        for (int e = 0; e < 4; e++) {
            int row = rowL + e * 32;
            uint32_t dst = (uint32_t)(row * 128) + (uint32_t)(ccL ^ ((row & 7) * 16));
            size_t srcA = (size_t)(m0 + row) * CIN + kk + (ccL >> 1);
            *(uint4*)(smem + SM_AHI + dst) = *(const uint4*)&g_whi[srcA];
            *(uint4*)(smem + SM_ALO + dst) = *(const uint4*)&g_wlo[srcA];
            size_t srcB = ((size_t)b * P + p0 + row) * CIN + kk + (ccL >> 1);
            *(uint4*)(smem + SM_BHI + dst) = *(const uint4*)&g_xhi[srcB];
            *(uint4*)(smem + SM_BLO + dst) = *(const uint4*)&g_xlo[srcB];
        }
        __syncthreads();

#pragma unroll
        for (int ks = 0; ks < 4; ks++) {
            const int colA = (ks * 32 + c16A);
            const int colB = (ks * 32 + c16B);
            uint32_t ah[2][4], al[2][4];
#pragma unroll
            for (int mf = 0; mf < 2; mf++) {
                uint32_t off = (uint32_t)(rowA[mf] * 128) +
                               (uint32_t)(colA ^ ((rowA[mf] & 7) * 16));
                LDSM4(ah[mf][0], ah[mf][1], ah[mf][2], ah[mf][3], sbase + SM_AHI + off);
                LDSM4(al[mf][0], al[mf][1], al[mf][2], al[mf][3], sbase + SM_ALO + off);
            }
            uint32_t bh[8][2], bl[8][2];
#pragma unroll
            for (int nfp = 0; nfp < 4; nfp++) {
                uint32_t off = (uint32_t)(rowB[nfp] * 128) +
                               (uint32_t)(colB ^ ((rowB[nfp] & 7) * 16));
                LDSM4(bh[2 * nfp][0], bh[2 * nfp][1], bh[2 * nfp + 1][0], bh[2 * nfp + 1][1],
                      sbase + SM_BHI + off);
                LDSM4(bl[2 * nfp][0], bl[2 * nfp][1], bl[2 * nfp + 1][0], bl[2 * nfp + 1][1],
                      sbase + SM_BLO + off);
            }
#pragma unroll
            for (int mf = 0; mf < 2; mf++)
#pragma unroll
                for (int nf = 0; nf < 8; nf++) {
                    MMA_BF16(acc[mf][nf], ah[mf], bh[nf]);
                    MMA_BF16(acc[mf][nf], ah[mf], bl[nf]);
                    MMA_BF16(acc[mf][nf], al[mf], bh[nf]);
                }
        }
        __syncthreads();
    }

    const int r = lid >> 2;
    const int cc = (lid & 3) * 2;
#pragma unroll
    for (int mf = 0; mf < 2; mf++) {
        int m1 = m0 + wm * 32 + mf * 16 + r;
        int m2 = m1 + 8;
        float bv1 = (m1 < MID) ? g_bias[m1] : 0.f;
        float bv2 = (m2 < MID) ? g_bias[m2] : 0.f;
#pragma unroll
        for (int nf = 0; nf < 8; nf++) {
            int p = p0 + wn * 64 + nf * 8 + cc;
            if (m1 < MID) {
                float2 v = make_float2(acc[mf][nf][0] + bv1, acc[mf][nf][1] + bv1);
                *(float2*)&g_y[((size_t)b * MID + m1) * P + p] = v;
            }
            if (m2 < MID) {
                float2 v = make_float2(acc[mf][nf][2] + bv2, acc[mf][nf][3] + bv2);
                *(float2*)&g_y[((size_t)b * MID + m2) * P + p] = v;
            }
        }
    }
}

// ---------------- K3: wgen1 via mma.sync with fused reflect-unfold gather ----------------
// t[b,g,p] = relu(bn2( cw1[g,:] . h[b,:,p] )), M=32, K=320 (5 chunks of 64), N=128/CTA.
#define W1_AH   0
#define W1_AL   20480
#define W1_BH   40960
#define W1_BL   57344
#define W1_C4   73728                       // int4 s_c4[320]: {ch, di, dj, bits(s)}
#define W1_CB   (W1_C4 + 320 * 16)          // float s_b[320]
#define W1_TOTAL (W1_CB + 320 * 4)          // 80128 B

__global__ __launch_bounds__(256) void wgen1_mma_kernel() {
    extern __shared__ char smem[];
    const uint32_t sbase = smem_u32(smem);
    int4*  s_c4 = (int4*)(smem + W1_C4);
    float* s_cb = (float*)(smem + W1_CB);
    const int tid = threadIdx.x;
    const int wid = tid >> 5;
    const int lid = tid & 31;
    const int b  = blockIdx.y;
    const int p0 = blockIdx.x * 128;
    const float* yb = g_y + (size_t)b * MID * P;

    // ---- A tiles (all 5 chunks): [c][32][64] swizzled 128B rows, hi & lo ----
#pragma unroll
    for (int e = 0; e < 5; e++) {
        int idx = tid + e * 256;        // 0..1279
        int c = idx >> 8, rem = idx & 255;
        int m = rem >> 3, kg = rem & 7;
        uint32_t dst = (uint32_t)(c * 4096 + m * 128) + (uint32_t)((kg * 16) ^ ((m & 7) * 16));
        size_t src = (size_t)m * MID + c * 64 + kg * 8;
        *(uint4*)(smem + W1_AH + dst) = *(const uint4*)&g_c1hi[src];
        *(uint4*)(smem + W1_AL + dst) = *(const uint4*)&g_c1lo[src];
    }
    // ---- per-k gather constants ----
    for (int k = tid; k < MID; k += 256) {
        int ch, di, dj;
        if (k < 32) { ch = k; di = 0; dj = 0; }
        else {
            int cc = k - 32;
            int rr = cc / 9, t9 = cc - rr * 9;
            ch = 32 + rr;
            di = t9 / 3 - 1;
            dj = t9 - (t9 / 3) * 3 - 1;
        }
        s_c4[k] = make_int4(ch, di, dj, __float_as_int(g_bn1s[k]));
        s_cb[k] = g_bn1b[k];
    }
    __syncthreads();

    float acc[2][2][4];
#pragma unroll
    for (int i = 0; i < 2; i++)
#pragma unroll
        for (int j = 0; j < 2; j++)
#pragma unroll
            for (int q = 0; q < 4; q++) acc[i][j][q] = 0.f;

    const int rowA[2] = { (lid & 15), 16 + (lid & 15) };
    const int c16A = (lid >> 4) * 16;
    const int rowB = wid * 16 + ((lid >> 4) * 8) + (lid & 7);
    const int c16B = ((lid >> 3) & 1) * 16;

    // fill-thread mapping: px = tid & 127, khalf = tid >> 7
    const int fpx = tid & 127;
    const int fkh = (tid >> 7) * 32;
    const int pi = (p0 + fpx) >> 6;
    const int pj = (p0 + fpx) & 63;

    for (int c = 0; c < 5; c++) {
        const int kk = c * 64;
        // ---- B tile fill: h[128 px][64 k] bf16 hi/lo, fused gather ----
#pragma unroll
        for (int e = 0; e < 16; e++) {
            int kloc0 = fkh + 2 * e;
            int k0 = kk + kloc0;
            int4 c40 = s_c4[k0];
            int4 c41 = s_c4[k0 + 1];
            float b0 = s_cb[k0], b1 = s_cb[k0 + 1];
            int i0 = pi + c40.y, j0 = pj + c40.z;
            i0 = min(abs(i0), 126 - i0); j0 = min(abs(j0), 126 - j0);
            int i1 = pi + c41.y, j1 = pj + c41.z;
            i1 = min(abs(i1), 126 - i1); j1 = min(abs(j1), 126 - j1);
            float v0 = yb[(size_t)c40.x * P + (i0 << 6) + j0];
            float v1 = yb[(size_t)c41.x * P + (i1 << 6) + j1];
            float h0 = fmaxf(fmaf(v0, __int_as_float(c40.w), b0), 0.f);
            float h1 = fmaxf(fmaf(v1, __int_as_float(c41.w), b1), 0.f);
            __nv_bfloat16 hh0 = __float2bfloat16(h0);
            __nv_bfloat16 hh1 = __float2bfloat16(h1);
            __nv_bfloat16 ll0 = __float2bfloat16(h0 - __bfloat162float(hh0));
            __nv_bfloat16 ll1 = __float2bfloat16(h1 - __bfloat162float(hh1));
            uint32_t dst = (uint32_t)(fpx * 128) + (uint32_t)((kloc0 * 2) ^ ((fpx & 7) * 16));
            *(__nv_bfloat162*)(smem + W1_BH + dst) = __nv_bfloat162(hh0, hh1);
            *(__nv_bfloat162*)(smem + W1_BL + dst) = __nv_bfloat162(ll0, ll1);
        }
        __syncthreads();

        const uint32_t abase = (uint32_t)(c * 4096);
#pragma unroll
        for (int ks = 0; ks < 4; ks++) {
            const int colA = ks * 32 + c16A;
            const int colB = ks * 32 + c16B;
            uint32_t ah[2][4], al[2][4];
#pragma unroll
            for (int mf = 0; mf < 2; mf++) {
                uint32_t off = abase + (uint32_t)(rowA[mf] * 128) +
                               (uint32_t)(colA ^ ((rowA[mf] & 7) * 16));
                LDSM4(ah[mf][0], ah[mf][1], ah[mf][2], ah[mf][3], sbase + W1_AH + off);
                LDSM4(al[mf][0], al[mf][1], al[mf][2], al[mf][3], sbase + W1_AL + off);
            }
            uint32_t bh[2][2], bl[2][2];
            {
                uint32_t off = (uint32_t)(rowB * 128) + (uint32_t)(colB ^ ((rowB & 7) * 16));
                LDSM4(bh[0][0], bh[0][1], bh[1][0], bh[1][1], sbase + W1_BH + off);
                LDSM4(bl[0][0], bl[0][1], bl[1][0], bl[1][1], sbase + W1_BL + off);
            }
#pragma unroll
            for (int mf = 0; mf < 2; mf++)
#pragma unroll
                for (int nf = 0; nf < 2; nf++) {
                    MMA_BF16(acc[mf][nf], ah[mf], bh[nf]);
                    MMA_BF16(acc[mf][nf], ah[mf], bl[nf]);
                    MMA_BF16(acc[mf][nf], al[mf], bh[nf]);
                }
        }
        __syncthreads();
    }

    // ---- epilogue: bn2 + relu, write g_t[b][g][p] ----
    const int r = lid >> 2;
    const int c2 = (lid & 3) * 2;
#pragma unroll
    for (int mf = 0; mf < 2; mf++) {
        int g1 = mf * 16 + r;
        int g2 = g1 + 8;
        float s1 = g_bn2s[g1], sb1 = g_bn2b[g1];
        float s2 = g_bn2s[g2], sb2 = g_bn2b[g2];
#pragma unroll
        for (int nf = 0; nf < 2; nf++) {
            int p = p0 + wid * 16 + nf * 8 + c2;
            float2 v1 = make_float2(fmaxf(fmaf(acc[mf][nf][0], s1, sb1), 0.f),
                                    fmaxf(fmaf(acc[mf][nf][1], s1, sb1), 0.f));
            *(float2*)&g_t[((size_t)b * GG + g1) * P + p] = v1;
            float2 v2 = make_float2(fmaxf(fmaf(acc[mf][nf][2], s2, sb2), 0.f),
                                    fmaxf(fmaf(acc[mf][nf][3], s2, sb2), 0.f));
            *(float2*)&g_t[((size_t)b * GG + g2) * P + p] = v2;
        }
    }
}

// ---------------- K4: w[b,o,p] = cw2[o,:] . t[b,:,p] + cb2[o] ----------------
__global__ __launch_bounds__(256) void wgen2_kernel(const float* __restrict__ cw2,
                                                    const float* __restrict__ cb2) {
    const int b  = blockIdx.y;
    const int p0 = blockIdx.x * 64;
    __shared__ float ts[GG][64];
    __shared__ float w2s[WOUT * GG];
    const int tid = threadIdx.x;

#pragma unroll
    for (int e = 0; e < 8; e++) {
        int idx = tid + e * 256;
        int g = idx >> 6, n = idx & 63;
        ts[g][n] = g_t[((size_t)b * GG + g) * P + p0 + n];
    }
    for (int idx = tid; idx < WOUT * GG; idx += 256) w2s[idx] = cw2[idx];
    __syncthreads();

    const int pp = tid & 63;
    const int q  = tid >> 6;
    float tv[GG];
#pragma unroll
    for (int g = 0; g < GG; g++) tv[g] = ts[g][pp];

    for (int o = q * 72; o < q * 72 + 72; o++) {
        float acc = cb2[o];
#pragma unroll
        for (int g = 0; g < GG; g++) acc += w2s[o * GG + g] * tv[g];
        g_w[((size_t)b * WOUT + o) * P + p0 + pp] = acc;
    }
}

// ---------------- K5: local grouped 3x3 conv (zero pad) ----------------
__global__ __launch_bounds__(256) void localconv_kernel(float* __restrict__ out) {
    const int bg = blockIdx.y;
    const int b = bg >> 5, g = bg & 31;
    const int p = blockIdx.x * 256 + threadIdx.x;
    const int i = p >> 6, j = p & 63;

    const float* wv = g_w + ((size_t)b * WOUT + g * 9) * P + p;
    float w[9];
#pragma unroll
    for (int k = 0; k < 9; k++) w[k] = wv[(size_t)k * P];

    const float* x3 = g_y + ((size_t)b * MID + 64 + g * SHAREC) * P;
    float* ob = out + ((size_t)b * OUTC + g * SHAREC) * P + p;

#pragma unroll
    for (int s = 0; s < SHAREC; s++) {
        const float* xc = x3 + (size_t)s * P;
        float acc = 0.f;
#pragma unroll
        for (int ki = 0; ki < 3; ki++) {
            int ii = i + ki - 1;
            if (ii < 0 || ii > 63) continue;
#pragma unroll
            for (int kj = 0; kj < 3; kj++) {
                int jj = j + kj - 1;
                if (jj < 0 || jj > 63) continue;
                acc += xc[(ii << 6) + jj] * w[ki * 3 + kj];
            }
        }
        ob[(size_t)s * P] = acc;
    }
}

// ---------------- launch ----------------
extern "C" void kernel_launch(void* const* d_in, const int* in_sizes, int n_in,
                              void* d_out, int out_size) {
    const float* x     = (const float*)d_in[0];
    const float* w1    = (const float*)d_in[1];
    const float* b1    = (const float*)d_in[2];
    const float* w2    = (const float*)d_in[3];
    const float* b2    = (const float*)d_in[4];
    const float* w3    = (const float*)d_in[5];
    const float* b3    = (const float*)d_in[6];
    const float* bn1_g = (const float*)d_in[7];
    const float* bn1_b = (const float*)d_in[8];
    const float* bn1_m = (const float*)d_in[9];
    const float* bn1_v = (const float*)d_in[10];
    const float* cw1   = (const float*)d_in[11];
    const float* bn2_g = (const float*)d_in[12];
    const float* bn2_b = (const float*)d_in[13];
    const float* bn2_m = (const float*)d_in[14];
    const float* bn2_v = (const float*)d_in[15];
    const float* cw2   = (const float*)d_in[16];
    const float* cb2   = (const float*)d_in[17];
    float* out = (float*)d_out;

    static int smem_set = 0;
    if (!smem_set) {
        cudaFuncSetAttribute(conv_mma_kernel,
                             cudaFuncAttributeMaxDynamicSharedMemorySize, SM_TOTAL);
        cudaFuncSetAttribute(wgen1_mma_kernel,
                             cudaFuncAttributeMaxDynamicSharedMemorySize, W1_TOTAL);
        smem_set = 1;
    }

    pack_kernel<<<6, 64>>>(w1, b1, w2, b2, w3, b3,
                           bn1_g, bn1_b, bn1_m, bn1_v,
                           bn2_g, bn2_b, bn2_m, bn2_v, cw1);
    {
        dim3 grid(P / 32, CIN / 64, BB);      // 128 x 4 x 8
        xconv_kernel<<<grid, 256>>>(x);
    }
    {
        dim3 grid(P / 128, MIDP / 128, BB);   // 32 x 3 x 8
        conv_mma_kernel<<<grid, 256, SM_TOTAL>>>();
    }
    {
        dim3 grid(P / 128, BB);               // 32 x 8
        wgen1_mma_kernel<<<grid, 256, W1_TOTAL>>>();
    }
    {
        dim3 grid(P / 64, BB);
        wgen2_kernel<<<grid, 256>>>(cw2, cb2);
    }
    {
        dim3 grid(P / 256, BB * GG);
        localconv_kernel<<<grid, 256>>>(out);
    }
}

// round 6
// speedup vs baseline: 1.1199x; 1.1199x over previous
#include <cuda_runtime.h>
#include <cuda_bf16.h>
#include <math.h>
#include <stdint.h>

#define BB    8
#define CIN   256
#define OUTC  256
#define SHAREC 8
#define GG    32
#define MID   320
#define MIDP  384
#define WOUT  288
#define P     4096

// ---------------- scratch (static device arrays; no allocation) ----------------
__device__ float g_y[(size_t)BB * MID * P];      // conv1x1 outputs [b][c][p]
__device__ float g_t[(size_t)BB * GG * P];       // weight-gen hidden
__device__ float g_bias[MIDP];
__device__ float g_bn1s[MID];
__device__ float g_bn1b[MID];
__device__ float g_bn2s[GG];
__device__ float g_bn2b[GG];
__device__ __nv_bfloat16 g_whi[MIDP * CIN];      // conv weights hi/lo, [m][k]
__device__ __nv_bfloat16 g_wlo[MIDP * CIN];
__device__ __nv_bfloat16 g_xhi[(size_t)BB * P * CIN];  // x transposed: [b][p][c]
__device__ __nv_bfloat16 g_xlo[(size_t)BB * P * CIN];
__device__ __nv_bfloat16 g_c1hi[GG * MID];       // cw1 hi/lo, [g][k]
__device__ __nv_bfloat16 g_c1lo[GG * MID];

__device__ __forceinline__ uint32_t smem_u32(const void* p) {
    uint32_t a;
    asm("{ .reg .u64 t; cvta.to.shared.u64 t, %1; cvt.u32.u64 %0, t; }" : "=r"(a) : "l"(p));
    return a;
}

#define LDSM4(r0, r1, r2, r3, addr) \
    asm volatile("ldmatrix.sync.aligned.m8n8.x4.shared.b16 {%0,%1,%2,%3}, [%4];" \
        : "=r"(r0), "=r"(r1), "=r"(r2), "=r"(r3) : "r"(addr))

#define MMA_BF16(d, a, b) \
    asm volatile("mma.sync.aligned.m16n8k16.row.col.f32.bf16.bf16.f32 " \
        "{%0,%1,%2,%3}, {%4,%5,%6,%7}, {%8,%9}, {%0,%1,%2,%3};" \
        : "+f"((d)[0]), "+f"((d)[1]), "+f"((d)[2]), "+f"((d)[3]) \
        : "r"((a)[0]), "r"((a)[1]), "r"((a)[2]), "r"((a)[3]), "r"((b)[0]), "r"((b)[1]))

// ---------------- K0a: pack + split weights (fully parallel, coalesced) ----------------
__global__ __launch_bounds__(256) void packw_kernel(const float* __restrict__ w1,
                                                    const float* __restrict__ w2,
                                                    const float* __restrict__ w3,
                                                    const float* __restrict__ cw1) {
    int idx = blockIdx.x * 256 + threadIdx.x;
    if (idx < MIDP * CIN) {
        int c = idx >> 8;           // CIN = 256
        int k = idx & 255;
        float v = 0.f;
        if (c < 32)       v = w1[c * CIN + k];
        else if (c < 64)  v = w2[(c - 32) * CIN + k];
        else if (c < MID) v = w3[(c - 64) * CIN + k];
        __nv_bfloat16 hi = __float2bfloat16(v);
        g_whi[idx] = hi;
        g_wlo[idx] = __float2bfloat16(v - __bfloat162float(hi));
    } else {
        int j = idx - MIDP * CIN;
        if (j < GG * MID) {
            float v = cw1[j];
            __nv_bfloat16 hi = __float2bfloat16(v);
            g_c1hi[j] = hi;
            g_c1lo[j] = __float2bfloat16(v - __bfloat162float(hi));
        }
    }
}

// ---------------- K0a': fold BN params + biases ----------------
__global__ void packbn_kernel(const float* __restrict__ b1, const float* __restrict__ b2,
                              const float* __restrict__ b3,
                              const float* __restrict__ bn1_g, const float* __restrict__ bn1_b,
                              const float* __restrict__ bn1_m, const float* __restrict__ bn1_v,
                              const float* __restrict__ bn2_g, const float* __restrict__ bn2_b,
                              const float* __restrict__ bn2_m, const float* __restrict__ bn2_v) {
    int c = blockIdx.x * 128 + threadIdx.x;
    if (c >= MID) return;
    g_bias[c] = (c < 32) ? b1[c] : (c < 64) ? b2[c - 32] : b3[c - 64];
    float s = bn1_g[c] * rsqrtf(bn1_v[c] + 1e-5f);
    g_bn1s[c] = s;
    g_bn1b[c] = bn1_b[c] - bn1_m[c] * s;
    if (c < GG) {
        float s2 = bn2_g[c] * rsqrtf(bn2_v[c] + 1e-5f);
        g_bn2s[c] = s2;
        g_bn2b[c] = bn2_b[c] - bn2_m[c] * s2;
    }
}

// ---------------- K0b: transpose + split-convert x -> [b][p][c] bf16 hi/lo ----------------
__global__ __launch_bounds__(256) void xconv_kernel(const float* __restrict__ x) {
    __shared__ float tile[64][33];
    const int b  = blockIdx.z;
    const int c0 = blockIdx.y * 64;
    const int p0 = blockIdx.x * 32;
    const int tid = threadIdx.x;
#pragma unroll
    for (int e = 0; e < 8; e++) {
        int idx = tid + e * 256;
        int c = idx >> 5, j = idx & 31;
        tile[c][j] = x[((size_t)b * CIN + c0 + c) * P + p0 + j];
    }
    __syncthreads();
#pragma unroll
    for (int e = 0; e < 4; e++) {
        int idx = tid + e * 256;
        int p = idx >> 5, cp = idx & 31;
        float f0 = tile[2 * cp][p], f1 = tile[2 * cp + 1][p];
        __nv_bfloat16 h0 = __float2bfloat16(f0);
        __nv_bfloat16 h1 = __float2bfloat16(f1);
        __nv_bfloat16 l0 = __float2bfloat16(f0 - __bfloat162float(h0));
        __nv_bfloat16 l1 = __float2bfloat16(f1 - __bfloat162float(h1));
        size_t off = ((size_t)b * P + p0 + p) * CIN + c0 + 2 * cp;
        *(__nv_bfloat162*)&g_xhi[off] = __nv_bfloat162(h0, h1);
        *(__nv_bfloat162*)&g_xlo[off] = __nv_bfloat162(l0, l1);
    }
}

// ---------------- K1: conv1x1 via mma.sync split-bf16 GEMM (proven) ----------------
#define KC 64
#define SM_AHI 0
#define SM_ALO 16384
#define SM_BHI 32768
#define SM_BLO 49152
#define SM_TOTAL 65536

__global__ __launch_bounds__(256) void conv_mma_kernel() {
    extern __shared__ char smem[];
    const uint32_t sbase = smem_u32(smem);
    const int tid = threadIdx.x;
    const int wid = tid >> 5;
    const int lid = tid & 31;
    const int b  = blockIdx.z;
    const int m0 = blockIdx.y * 128;
    const int p0 = blockIdx.x * 128;
    const int wm = wid & 3;
    const int wn = wid >> 2;

    float acc[2][8][4];
#pragma unroll
    for (int i = 0; i < 2; i++)
#pragma unroll
        for (int j = 0; j < 8; j++)
#pragma unroll
            for (int q = 0; q < 4; q++) acc[i][j][q] = 0.f;

    const int rowA[2] = { wm * 32 + (lid & 15), wm * 32 + 16 + (lid & 15) };
    const int c16A = (lid >> 4) * 16;
    int rowB[4];
#pragma unroll
    for (int nfp = 0; nfp < 4; nfp++)
        rowB[nfp] = wn * 64 + nfp * 16 + ((lid >> 4) * 8) + (lid & 7);
    const int c16B = ((lid >> 3) & 1) * 16;

    const int rowL = tid >> 3;
    const int ccL  = (tid & 7) * 16;

    for (int c = 0; c < 4; c++) {
        const int kk = c * KC;
#pragma unroll
        for (int e = 0; e < 4; e++) {
            int row = rowL + e * 32;
            uint32_t dst = (uint32_t)(row * 128) + (uint32_t)(ccL ^ ((row & 7) * 16));
            size_t srcA = (size_t)(m0 + row) * CIN + kk + (ccL >> 1);
            *(uint4*)(smem + SM_AHI + dst) = *(const uint4*)&g_whi[srcA];
            *(uint4*)(smem + SM_ALO + dst) = *(const uint4*)&g_wlo[srcA];
            size_t srcB = ((size_t)b * P + p0 + row) * CIN + kk + (ccL >> 1);
            *(uint4*)(smem + SM_BHI + dst) = *(const uint4*)&g_xhi[srcB];
            *(uint4*)(smem + SM_BLO + dst) = *(const uint4*)&g_xlo[srcB];
        }
        __syncthreads();

#pragma unroll
        for (int ks = 0; ks < 4; ks++) {
            const int colA = (ks * 32 + c16A);
            const int colB = (ks * 32 + c16B);
            uint32_t ah[2][4], al[2][4];
#pragma unroll
            for (int mf = 0; mf < 2; mf++) {
                uint32_t off = (uint32_t)(rowA[mf] * 128) +
                               (uint32_t)(colA ^ ((rowA[mf] & 7) * 16));
                LDSM4(ah[mf][0], ah[mf][1], ah[mf][2], ah[mf][3], sbase + SM_AHI + off);
                LDSM4(al[mf][0], al[mf][1], al[mf][2], al[mf][3], sbase + SM_ALO + off);
            }
            uint32_t bh[8][2], bl[8][2];
#pragma unroll
            for (int nfp = 0; nfp < 4; nfp++) {
                uint32_t off = (uint32_t)(rowB[nfp] * 128) +
                               (uint32_t)(colB ^ ((rowB[nfp] & 7) * 16));
                LDSM4(bh[2 * nfp][0], bh[2 * nfp][1], bh[2 * nfp + 1][0], bh[2 * nfp + 1][1],
                      sbase + SM_BHI + off);
                LDSM4(bl[2 * nfp][0], bl[2 * nfp][1], bl[2 * nfp + 1][0], bl[2 * nfp + 1][1],
                      sbase + SM_BLO + off);
            }
#pragma unroll
            for (int mf = 0; mf < 2; mf++)
#pragma unroll
                for (int nf = 0; nf < 8; nf++) {
                    MMA_BF16(acc[mf][nf], ah[mf], bh[nf]);
                    MMA_BF16(acc[mf][nf], ah[mf], bl[nf]);
                    MMA_BF16(acc[mf][nf], al[mf], bh[nf]);
                }
        }
        __syncthreads();
    }

    const int r = lid >> 2;
    const int cc = (lid & 3) * 2;
#pragma unroll
    for (int mf = 0; mf < 2; mf++) {
        int m1 = m0 + wm * 32 + mf * 16 + r;
        int m2 = m1 + 8;
        float bv1 = (m1 < MID) ? g_bias[m1] : 0.f;
        float bv2 = (m2 < MID) ? g_bias[m2] : 0.f;
#pragma unroll
        for (int nf = 0; nf < 8; nf++) {
            int p = p0 + wn * 64 + nf * 8 + cc;
            if (m1 < MID) {
                float2 v = make_float2(acc[mf][nf][0] + bv1, acc[mf][nf][1] + bv1);
                *(float2*)&g_y[((size_t)b * MID + m1) * P + p] = v;
            }
            if (m2 < MID) {
                float2 v = make_float2(acc[mf][nf][2] + bv2, acc[mf][nf][3] + bv2);
                *(float2*)&g_y[((size_t)b * MID + m2) * P + p] = v;
            }
        }
    }
}

// ---------------- K3: wgen1 via mma.sync with fused reflect-unfold gather (proven) ----------------
#define W1_AH   0
#define W1_AL   20480
#define W1_BH   40960
#define W1_BL   57344
#define W1_C4   73728
#define W1_CB   (W1_C4 + 320 * 16)
#define W1_TOTAL (W1_CB + 320 * 4)

__global__ __launch_bounds__(256) void wgen1_mma_kernel() {
    extern __shared__ char smem[];
    const uint32_t sbase = smem_u32(smem);
    int4*  s_c4 = (int4*)(smem + W1_C4);
    float* s_cb = (float*)(smem + W1_CB);
    const int tid = threadIdx.x;
    const int wid = tid >> 5;
    const int lid = tid & 31;
    const int b  = blockIdx.y;
    const int p0 = blockIdx.x * 128;
    const float* yb = g_y + (size_t)b * MID * P;

#pragma unroll
    for (int e = 0; e < 5; e++) {
        int idx = tid + e * 256;
        int c = idx >> 8, rem = idx & 255;
        int m = rem >> 3, kg = rem & 7;
        uint32_t dst = (uint32_t)(c * 4096 + m * 128) + (uint32_t)((kg * 16) ^ ((m & 7) * 16));
        size_t src = (size_t)m * MID + c * 64 + kg * 8;
        *(uint4*)(smem + W1_AH + dst) = *(const uint4*)&g_c1hi[src];
        *(uint4*)(smem + W1_AL + dst) = *(const uint4*)&g_c1lo[src];
    }
    for (int k = tid; k < MID; k += 256) {
        int ch, di, dj;
        if (k < 32) { ch = k; di = 0; dj = 0; }
        else {
            int cc = k - 32;
            int rr = cc / 9, t9 = cc - rr * 9;
            ch = 32 + rr;
            di = t9 / 3 - 1;
            dj = t9 - (t9 / 3) * 3 - 1;
        }
        s_c4[k] = make_int4(ch, di, dj, __float_as_int(g_bn1s[k]));
        s_cb[k] = g_bn1b[k];
    }
    __syncthreads();

    float acc[2][2][4];
#pragma unroll
    for (int i = 0; i < 2; i++)
#pragma unroll
        for (int j = 0; j < 2; j++)
#pragma unroll
            for (int q = 0; q < 4; q++) acc[i][j][q] = 0.f;

    const int rowA[2] = { (lid & 15), 16 + (lid & 15) };
    const int c16A = (lid >> 4) * 16;
    const int rowB = wid * 16 + ((lid >> 4) * 8) + (lid & 7);
    const int c16B = ((lid >> 3) & 1) * 16;

    const int fpx = tid & 127;
    const int fkh = (tid >> 7) * 32;
    const int pi = (p0 + fpx) >> 6;
    const int pj = (p0 + fpx) & 63;

    for (int c = 0; c < 5; c++) {
        const int kk = c * 64;
#pragma unroll
        for (int e = 0; e < 16; e++) {
            int kloc0 = fkh + 2 * e;
            int k0 = kk + kloc0;
            int4 c40 = s_c4[k0];
            int4 c41 = s_c4[k0 + 1];
            float b0 = s_cb[k0], b1 = s_cb[k0 + 1];
            int i0 = pi + c40.y, j0 = pj + c40.z;
            i0 = min(abs(i0), 126 - i0); j0 = min(abs(j0), 126 - j0);
            int i1 = pi + c41.y, j1 = pj + c41.z;
            i1 = min(abs(i1), 126 - i1); j1 = min(abs(j1), 126 - j1);
            float v0 = yb[(size_t)c40.x * P + (i0 << 6) + j0];
            float v1 = yb[(size_t)c41.x * P + (i1 << 6) + j1];
            float h0 = fmaxf(fmaf(v0, __int_as_float(c40.w), b0), 0.f);
            float h1 = fmaxf(fmaf(v1, __int_as_float(c41.w), b1), 0.f);
            __nv_bfloat16 hh0 = __float2bfloat16(h0);
            __nv_bfloat16 hh1 = __float2bfloat16(h1);
            __nv_bfloat16 ll0 = __float2bfloat16(h0 - __bfloat162float(hh0));
            __nv_bfloat16 ll1 = __float2bfloat16(h1 - __bfloat162float(hh1));
            uint32_t dst = (uint32_t)(fpx * 128) + (uint32_t)((kloc0 * 2) ^ ((fpx & 7) * 16));
            *(__nv_bfloat162*)(smem + W1_BH + dst) = __nv_bfloat162(hh0, hh1);
            *(__nv_bfloat162*)(smem + W1_BL + dst) = __nv_bfloat162(ll0, ll1);
        }
        __syncthreads();

        const uint32_t abase = (uint32_t)(c * 4096);
#pragma unroll
        for (int ks = 0; ks < 4; ks++) {
            const int colA = ks * 32 + c16A;
            const int colB = ks * 32 + c16B;
            uint32_t ah[2][4], al[2][4];
#pragma unroll
            for (int mf = 0; mf < 2; mf++) {
                uint32_t off = abase + (uint32_t)(rowA[mf] * 128) +
                               (uint32_t)(colA ^ ((rowA[mf] & 7) * 16));
                LDSM4(ah[mf][0], ah[mf][1], ah[mf][2], ah[mf][3], sbase + W1_AH + off);
                LDSM4(al[mf][0], al[mf][1], al[mf][2], al[mf][3], sbase + W1_AL + off);
            }
            uint32_t bh[2][2], bl[2][2];
            {
                uint32_t off = (uint32_t)(rowB * 128) + (uint32_t)(colB ^ ((rowB & 7) * 16));
                LDSM4(bh[0][0], bh[0][1], bh[1][0], bh[1][1], sbase + W1_BH + off);
                LDSM4(bl[0][0], bl[0][1], bl[1][0], bl[1][1], sbase + W1_BL + off);
            }
#pragma unroll
            for (int mf = 0; mf < 2; mf++)
#pragma unroll
                for (int nf = 0; nf < 2; nf++) {
                    MMA_BF16(acc[mf][nf], ah[mf], bh[nf]);
                    MMA_BF16(acc[mf][nf], ah[mf], bl[nf]);
                    MMA_BF16(acc[mf][nf], al[mf], bh[nf]);
                }
        }
        __syncthreads();
    }

    const int r = lid >> 2;
    const int c2 = (lid & 3) * 2;
#pragma unroll
    for (int mf = 0; mf < 2; mf++) {
        int g1 = mf * 16 + r;
        int g2 = g1 + 8;
        float s1 = g_bn2s[g1], sb1 = g_bn2b[g1];
        float s2 = g_bn2s[g2], sb2 = g_bn2b[g2];
#pragma unroll
        for (int nf = 0; nf < 2; nf++) {
            int p = p0 + wid * 16 + nf * 8 + c2;
            float2 v1 = make_float2(fmaxf(fmaf(acc[mf][nf][0], s1, sb1), 0.f),
                                    fmaxf(fmaf(acc[mf][nf][1], s1, sb1), 0.f));
            *(float2*)&g_t[((size_t)b * GG + g1) * P + p] = v1;
            float2 v2 = make_float2(fmaxf(fmaf(acc[mf][nf][2], s2, sb2), 0.f),
                                    fmaxf(fmaf(acc[mf][nf][3], s2, sb2), 0.f));
            *(float2*)&g_t[((size_t)b * GG + g2) * P + p] = v2;
        }
    }
}

// ---------------- K4+K5 fused: per-pixel weight gen + local grouped 3x3 conv ----------------
// Block: one image row (64 px), one batch. 256 threads = 64 px x 4 group-quarters.
// Each thread: compute w[9] per group in registers from t-column, apply conv, write out.
__global__ __launch_bounds__(256) void wgen2_local_kernel(const float* __restrict__ cw2,
                                                          const float* __restrict__ cb2,
                                                          float* __restrict__ out) {
    __shared__ float ts[GG][64];       // 8 KB
    __shared__ float w2s[WOUT * GG];   // 36 KB
    __shared__ float cbs[WOUT];        // ~1.2 KB
    const int b  = blockIdx.y;
    const int p0 = blockIdx.x * 64;    // one row: i = blockIdx.x
    const int tid = threadIdx.x;

#pragma unroll
    for (int e = 0; e < 8; e++) {
        int idx = tid + e * 256;
        int g = idx >> 6, n = idx & 63;
        ts[g][n] = g_t[((size_t)b * GG + g) * P + p0 + n];
    }
    for (int idx = tid; idx < WOUT * GG; idx += 256) w2s[idx] = cw2[idx];
    for (int idx = tid; idx < WOUT; idx += 256) cbs[idx] = cb2[idx];
    __syncthreads();

    const int pp = tid & 63;
    const int q  = tid >> 6;           // 0..3 -> groups q*8 .. q*8+7
    const int i  = blockIdx.x;         // row index
    const int j  = pp;

    float tv[GG];
#pragma unroll
    for (int g = 0; g < GG; g++) tv[g] = ts[g][pp];

#pragma unroll
    for (int g8 = 0; g8 < 8; g8++) {
        const int g = q * 8 + g8;
        // per-pixel 3x3 kernel for this group
        float w[9];
#pragma unroll
        for (int t9 = 0; t9 < 9; t9++) {
            float acc = cbs[g * 9 + t9];
            const float4* wrow = (const float4*)&w2s[(g * 9 + t9) * GG];
#pragma unroll
            for (int k4 = 0; k4 < 8; k4++) {
                float4 wv = wrow[k4];
                acc += wv.x * tv[4 * k4] + wv.y * tv[4 * k4 + 1]
                     + wv.z * tv[4 * k4 + 2] + wv.w * tv[4 * k4 + 3];
            }
            w[t9] = acc;
        }
        // local 3x3 conv (zero pad) over this group's 8 shared channels
        const float* x3 = g_y + ((size_t)b * MID + 64 + g * SHAREC) * P;
        float* ob = out + ((size_t)b * OUTC + g * SHAREC) * P + p0 + pp;
#pragma unroll
        for (int s = 0; s < SHAREC; s++) {
            const float* xc = x3 + (size_t)s * P;
            float acc = 0.f;
#pragma unroll
            for (int ki = 0; ki < 3; ki++) {
                int ii = i + ki - 1;
                if (ii < 0 || ii > 63) continue;
#pragma unroll
                for (int kj = 0; kj < 3; kj++) {
                    int jj = j + kj - 1;
                    if (jj < 0 || jj > 63) continue;
                    acc += xc[(ii << 6) + jj] * w[ki * 3 + kj];
                }
            }
            ob[(size_t)s * P] = acc;
        }
    }
}

// ---------------- launch ----------------
extern "C" void kernel_launch(void* const* d_in, const int* in_sizes, int n_in,
                              void* d_out, int out_size) {
    const float* x     = (const float*)d_in[0];
    const float* w1    = (const float*)d_in[1];
    const float* b1    = (const float*)d_in[2];
    const float* w2    = (const float*)d_in[3];
    const float* b2    = (const float*)d_in[4];
    const float* w3    = (const float*)d_in[5];
    const float* b3    = (const float*)d_in[6];
    const float* bn1_g = (const float*)d_in[7];
    const float* bn1_b = (const float*)d_in[8];
    const float* bn1_m = (const float*)d_in[9];
    const float* bn1_v = (const float*)d_in[10];
    const float* cw1   = (const float*)d_in[11];
    const float* bn2_g = (const float*)d_in[12];
    const float* bn2_b = (const float*)d_in[13];
    const float* bn2_m = (const float*)d_in[14];
    const float* bn2_v = (const float*)d_in[15];
    const float* cw2   = (const float*)d_in[16];
    const float* cb2   = (const float*)d_in[17];
    float* out = (float*)d_out;

    static int smem_set = 0;
    if (!smem_set) {
        cudaFuncSetAttribute(conv_mma_kernel,
                             cudaFuncAttributeMaxDynamicSharedMemorySize, SM_TOTAL);
        cudaFuncSetAttribute(wgen1_mma_kernel,
                             cudaFuncAttributeMaxDynamicSharedMemorySize, W1_TOTAL);
        smem_set = 1;
    }

    packw_kernel<<<(MIDP * CIN + GG * MID + 255) / 256, 256>>>(w1, w2, w3, cw1);
    packbn_kernel<<<3, 128>>>(b1, b2, b3,
                              bn1_g, bn1_b, bn1_m, bn1_v,
                              bn2_g, bn2_b, bn2_m, bn2_v);
    {
        dim3 grid(P / 32, CIN / 64, BB);      // 128 x 4 x 8
        xconv_kernel<<<grid, 256>>>(x);
    }
    {
        dim3 grid(P / 128, MIDP / 128, BB);   // 32 x 3 x 8
        conv_mma_kernel<<<grid, 256, SM_TOTAL>>>();
    }
    {
        dim3 grid(P / 128, BB);               // 32 x 8
        wgen1_mma_kernel<<<grid, 256, W1_TOTAL>>>();
    }
    {
        dim3 grid(P / 64, BB);                // 64 x 8
        wgen2_local_kernel<<<grid, 256>>>(cw2, cb2, out);
    }
}

// round 7
// speedup vs baseline: 1.1694x; 1.0442x over previous
#include <cuda_runtime.h>
#include <cuda_bf16.h>
#include <math.h>
#include <stdint.h>

#define BB    8
#define CIN   256
#define OUTC  256
#define SHAREC 8
#define GG    32
#define MID   320
#define MIDP  384
#define WOUT  288
#define P     4096

// ---------------- scratch (static device arrays; no allocation) ----------------
__device__ float g_y[(size_t)BB * MID * P];      // conv1x1 outputs [b][c][p]
__device__ float g_t[(size_t)BB * GG * P];       // weight-gen hidden
__device__ float g_bias[MIDP];
__device__ float g_bn1s[MID];
__device__ float g_bn1b[MID];
__device__ float g_bn2s[GG];
__device__ float g_bn2b[GG];
__device__ __nv_bfloat16 g_whi[MIDP * CIN];      // conv weights hi/lo, [m][k]
__device__ __nv_bfloat16 g_wlo[MIDP * CIN];
__device__ __nv_bfloat16 g_xhi[(size_t)BB * P * CIN];  // x transposed: [b][p][c]
__device__ __nv_bfloat16 g_xlo[(size_t)BB * P * CIN];
__device__ __nv_bfloat16 g_c1hi[GG * MID];       // cw1 hi/lo, [g][k]
__device__ __nv_bfloat16 g_c1lo[GG * MID];

__device__ __forceinline__ uint32_t smem_u32(const void* p) {
    uint32_t a;
    asm("{ .reg .u64 t; cvta.to.shared.u64 t, %1; cvt.u32.u64 %0, t; }" : "=r"(a) : "l"(p));
    return a;
}

#define LDSM4(r0, r1, r2, r3, addr) \
    asm volatile("ldmatrix.sync.aligned.m8n8.x4.shared.b16 {%0,%1,%2,%3}, [%4];" \
        : "=r"(r0), "=r"(r1), "=r"(r2), "=r"(r3) : "r"(addr))

#define MMA_BF16(d, a, b) \
    asm volatile("mma.sync.aligned.m16n8k16.row.col.f32.bf16.bf16.f32 " \
        "{%0,%1,%2,%3}, {%4,%5,%6,%7}, {%8,%9}, {%0,%1,%2,%3};" \
        : "+f"((d)[0]), "+f"((d)[1]), "+f"((d)[2]), "+f"((d)[3]) \
        : "r"((a)[0]), "r"((a)[1]), "r"((a)[2]), "r"((a)[3]), "r"((b)[0]), "r"((b)[1]))

#define CP_ASYNC16(saddr, gptr) \
    asm volatile("cp.async.cg.shared.global [%0], [%1], 16;" :: "r"(saddr), "l"(gptr))
#define CP_COMMIT() asm volatile("cp.async.commit_group;" ::: "memory")
#define CP_WAIT1()  asm volatile("cp.async.wait_group 1;" ::: "memory")
#define CP_WAIT0()  asm volatile("cp.async.wait_group 0;" ::: "memory")

// ---------------- K0a: pack + split weights (fully parallel, coalesced) ----------------
__global__ __launch_bounds__(256) void packw_kernel(const float* __restrict__ w1,
                                                    const float* __restrict__ w2,
                                                    const float* __restrict__ w3,
                                                    const float* __restrict__ cw1) {
    int idx = blockIdx.x * 256 + threadIdx.x;
    if (idx < MIDP * CIN) {
        int c = idx >> 8;
        int k = idx & 255;
        float v = 0.f;
        if (c < 32)       v = w1[c * CIN + k];
        else if (c < 64)  v = w2[(c - 32) * CIN + k];
        else if (c < MID) v = w3[(c - 64) * CIN + k];
        __nv_bfloat16 hi = __float2bfloat16(v);
        g_whi[idx] = hi;
        g_wlo[idx] = __float2bfloat16(v - __bfloat162float(hi));
    } else {
        int j = idx - MIDP * CIN;
        if (j < GG * MID) {
            float v = cw1[j];
            __nv_bfloat16 hi = __float2bfloat16(v);
            g_c1hi[j] = hi;
            g_c1lo[j] = __float2bfloat16(v - __bfloat162float(hi));
        }
    }
}

// ---------------- K0a': fold BN params + biases ----------------
__global__ void packbn_kernel(const float* __restrict__ b1, const float* __restrict__ b2,
                              const float* __restrict__ b3,
                              const float* __restrict__ bn1_g, const float* __restrict__ bn1_b,
                              const float* __restrict__ bn1_m, const float* __restrict__ bn1_v,
                              const float* __restrict__ bn2_g, const float* __restrict__ bn2_b,
                              const float* __restrict__ bn2_m, const float* __restrict__ bn2_v) {
    int c = blockIdx.x * 128 + threadIdx.x;
    if (c >= MID) return;
    g_bias[c] = (c < 32) ? b1[c] : (c < 64) ? b2[c - 32] : b3[c - 64];
    float s = bn1_g[c] * rsqrtf(bn1_v[c] + 1e-5f);
    g_bn1s[c] = s;
    g_bn1b[c] = bn1_b[c] - bn1_m[c] * s;
    if (c < GG) {
        float s2 = bn2_g[c] * rsqrtf(bn2_v[c] + 1e-5f);
        g_bn2s[c] = s2;
        g_bn2b[c] = bn2_b[c] - bn2_m[c] * s2;
    }
}

// ---------------- K0b: transpose + split-convert x -> [b][p][c] bf16 hi/lo ----------------
__global__ __launch_bounds__(256) void xconv_kernel(const float* __restrict__ x) {
    __shared__ float tile[64][33];
    const int b  = blockIdx.z;
    const int c0 = blockIdx.y * 64;
    const int p0 = blockIdx.x * 32;
    const int tid = threadIdx.x;
#pragma unroll
    for (int e = 0; e < 8; e++) {
        int idx = tid + e * 256;
        int c = idx >> 5, j = idx & 31;
        tile[c][j] = x[((size_t)b * CIN + c0 + c) * P + p0 + j];
    }
    __syncthreads();
#pragma unroll
    for (int e = 0; e < 4; e++) {
        int idx = tid + e * 256;
        int p = idx >> 5, cp = idx & 31;
        float f0 = tile[2 * cp][p], f1 = tile[2 * cp + 1][p];
        __nv_bfloat16 h0 = __float2bfloat16(f0);
        __nv_bfloat16 h1 = __float2bfloat16(f1);
        __nv_bfloat16 l0 = __float2bfloat16(f0 - __bfloat162float(h0));
        __nv_bfloat16 l1 = __float2bfloat16(f1 - __bfloat162float(h1));
        size_t off = ((size_t)b * P + p0 + p) * CIN + c0 + 2 * cp;
        *(__nv_bfloat162*)&g_xhi[off] = __nv_bfloat162(h0, h1);
        *(__nv_bfloat162*)&g_xlo[off] = __nv_bfloat162(l0, l1);
    }
}

// ---------------- K1: conv1x1 via mma.sync split-bf16 GEMM, cp.async double-buffered ----------------
#define KC 64
#define ST_AHI 0
#define ST_ALO 16384
#define ST_BHI 32768
#define ST_BLO 49152
#define STAGE  65536
#define SM_TOTAL (2 * STAGE)

__global__ __launch_bounds__(256) void conv_mma_kernel() {
    extern __shared__ char smem[];
    const uint32_t sbase = smem_u32(smem);
    const int tid = threadIdx.x;
    const int wid = tid >> 5;
    const int lid = tid & 31;
    const int b  = blockIdx.z;
    const int m0 = blockIdx.y * 128;
    const int p0 = blockIdx.x * 128;
    const int wm = wid & 3;
    const int wn = wid >> 2;

    float acc[2][8][4];
#pragma unroll
    for (int i = 0; i < 2; i++)
#pragma unroll
        for (int j = 0; j < 8; j++)
#pragma unroll
            for (int q = 0; q < 4; q++) acc[i][j][q] = 0.f;

    const int rowA[2] = { wm * 32 + (lid & 15), wm * 32 + 16 + (lid & 15) };
    const int c16A = (lid >> 4) * 16;
    int rowB[4];
#pragma unroll
    for (int nfp = 0; nfp < 4; nfp++)
        rowB[nfp] = wn * 64 + nfp * 16 + ((lid >> 4) * 8) + (lid & 7);
    const int c16B = ((lid >> 3) & 1) * 16;

    const int rowL = tid >> 3;
    const int ccL  = (tid & 7) * 16;

    // precompute per-thread load dst offsets (stage-relative) and sources
    uint32_t ldst[4];
    const __nv_bfloat16 *srcAh[4], *srcAl[4], *srcBh[4], *srcBl[4];
#pragma unroll
    for (int e = 0; e < 4; e++) {
        int row = rowL + e * 32;
        ldst[e] = (uint32_t)(row * 128) + (uint32_t)(ccL ^ ((row & 7) * 16));
        size_t sA = (size_t)(m0 + row) * CIN + (ccL >> 1);
        size_t sB = ((size_t)b * P + p0 + row) * CIN + (ccL >> 1);
        srcAh[e] = &g_whi[sA]; srcAl[e] = &g_wlo[sA];
        srcBh[e] = &g_xhi[sB]; srcBl[e] = &g_xlo[sB];
    }

    // issue chunk c into stage s
    auto issue = [&](int c, int s) {
        const uint32_t stb = sbase + (uint32_t)(s * STAGE);
        const int koff = c * KC;   // bf16 element offset along k
#pragma unroll
        for (int e = 0; e < 4; e++) {
            CP_ASYNC16(stb + ST_AHI + ldst[e], srcAh[e] + koff);
            CP_ASYNC16(stb + ST_ALO + ldst[e], srcAl[e] + koff);
            CP_ASYNC16(stb + ST_BHI + ldst[e], srcBh[e] + koff);
            CP_ASYNC16(stb + ST_BLO + ldst[e], srcBl[e] + koff);
        }
        CP_COMMIT();
    };

    issue(0, 0);
    for (int c = 0; c < 4; c++) {
        if (c < 3) { issue(c + 1, (c + 1) & 1); CP_WAIT1(); }
        else       { CP_WAIT0(); }
        __syncthreads();

        const uint32_t stb = sbase + (uint32_t)((c & 1) * STAGE);
#pragma unroll
        for (int ks = 0; ks < 4; ks++) {
            const int colA = (ks * 32 + c16A);
            const int colB = (ks * 32 + c16B);
            uint32_t ah[2][4], al[2][4];
#pragma unroll
            for (int mf = 0; mf < 2; mf++) {
                uint32_t off = (uint32_t)(rowA[mf] * 128) +
                               (uint32_t)(colA ^ ((rowA[mf] & 7) * 16));
                LDSM4(ah[mf][0], ah[mf][1], ah[mf][2], ah[mf][3], stb + ST_AHI + off);
                LDSM4(al[mf][0], al[mf][1], al[mf][2], al[mf][3], stb + ST_ALO + off);
            }
            uint32_t bh[8][2], bl[8][2];
#pragma unroll
            for (int nfp = 0; nfp < 4; nfp++) {
                uint32_t off = (uint32_t)(rowB[nfp] * 128) +
                               (uint32_t)(colB ^ ((rowB[nfp] & 7) * 16));
                LDSM4(bh[2 * nfp][0], bh[2 * nfp][1], bh[2 * nfp + 1][0], bh[2 * nfp + 1][1],
                      stb + ST_BHI + off);
                LDSM4(bl[2 * nfp][0], bl[2 * nfp][1], bl[2 * nfp + 1][0], bl[2 * nfp + 1][1],
                      stb + ST_BLO + off);
            }
#pragma unroll
            for (int mf = 0; mf < 2; mf++)
#pragma unroll
                for (int nf = 0; nf < 8; nf++) {
                    MMA_BF16(acc[mf][nf], ah[mf], bh[nf]);
                    MMA_BF16(acc[mf][nf], ah[mf], bl[nf]);
                    MMA_BF16(acc[mf][nf], al[mf], bh[nf]);
                }
        }
        __syncthreads();
    }

    const int r = lid >> 2;
    const int cc = (lid & 3) * 2;
#pragma unroll
    for (int mf = 0; mf < 2; mf++) {
        int m1 = m0 + wm * 32 + mf * 16 + r;
        int m2 = m1 + 8;
        float bv1 = (m1 < MID) ? g_bias[m1] : 0.f;
        float bv2 = (m2 < MID) ? g_bias[m2] : 0.f;
#pragma unroll
        for (int nf = 0; nf < 8; nf++) {
            int p = p0 + wn * 64 + nf * 8 + cc;
            if (m1 < MID) {
                float2 v = make_float2(acc[mf][nf][0] + bv1, acc[mf][nf][1] + bv1);
                *(float2*)&g_y[((size_t)b * MID + m1) * P + p] = v;
            }
            if (m2 < MID) {
                float2 v = make_float2(acc[mf][nf][2] + bv2, acc[mf][nf][3] + bv2);
                *(float2*)&g_y[((size_t)b * MID + m2) * P + p] = v;
            }
        }
    }
}

// ---------------- K3: wgen1 via mma.sync with fused reflect-unfold gather (proven) ----------------
#define W1_AH   0
#define W1_AL   20480
#define W1_BH   40960
#define W1_BL   57344
#define W1_C4   73728
#define W1_CB   (W1_C4 + 320 * 16)
#define W1_TOTAL (W1_CB + 320 * 4)

__global__ __launch_bounds__(256) void wgen1_mma_kernel() {
    extern __shared__ char smem[];
    const uint32_t sbase = smem_u32(smem);
    int4*  s_c4 = (int4*)(smem + W1_C4);
    float* s_cb = (float*)(smem + W1_CB);
    const int tid = threadIdx.x;
    const int wid = tid >> 5;
    const int lid = tid & 31;
    const int b  = blockIdx.y;
    const int p0 = blockIdx.x * 128;
    const float* yb = g_y + (size_t)b * MID * P;

#pragma unroll
    for (int e = 0; e < 5; e++) {
        int idx = tid + e * 256;
        int c = idx >> 8, rem = idx & 255;
        int m = rem >> 3, kg = rem & 7;
        uint32_t dst = (uint32_t)(c * 4096 + m * 128) + (uint32_t)((kg * 16) ^ ((m & 7) * 16));
        size_t src = (size_t)m * MID + c * 64 + kg * 8;
        *(uint4*)(smem + W1_AH + dst) = *(const uint4*)&g_c1hi[src];
        *(uint4*)(smem + W1_AL + dst) = *(const uint4*)&g_c1lo[src];
    }
    for (int k = tid; k < MID; k += 256) {
        int ch, di, dj;
        if (k < 32) { ch = k; di = 0; dj = 0; }
        else {
            int cc = k - 32;
            int rr = cc / 9, t9 = cc - rr * 9;
            ch = 32 + rr;
            di = t9 / 3 - 1;
            dj = t9 - (t9 / 3) * 3 - 1;
        }
        s_c4[k] = make_int4(ch, di, dj, __float_as_int(g_bn1s[k]));
        s_cb[k] = g_bn1b[k];
    }
    __syncthreads();

    float acc[2][2][4];
#pragma unroll
    for (int i = 0; i < 2; i++)
#pragma unroll
        for (int j = 0; j < 2; j++)
#pragma unroll
            for (int q = 0; q < 4; q++) acc[i][j][q] = 0.f;

    const int rowA[2] = { (lid & 15), 16 + (lid & 15) };
    const int c16A = (lid >> 4) * 16;
    const int rowB = wid * 16 + ((lid >> 4) * 8) + (lid & 7);
    const int c16B = ((lid >> 3) & 1) * 16;

    const int fpx = tid & 127;
    const int fkh = (tid >> 7) * 32;
    const int pi = (p0 + fpx) >> 6;
    const int pj = (p0 + fpx) & 63;

    for (int c = 0; c < 5; c++) {
        const int kk = c * 64;
#pragma unroll
        for (int e = 0; e < 16; e++) {
            int kloc0 = fkh + 2 * e;
            int k0 = kk + kloc0;
            int4 c40 = s_c4[k0];
            int4 c41 = s_c4[k0 + 1];
            float b0 = s_cb[k0], b1 = s_cb[k0 + 1];
            int i0 = pi + c40.y, j0 = pj + c40.z;
            i0 = min(abs(i0), 126 - i0); j0 = min(abs(j0), 126 - j0);
            int i1 = pi + c41.y, j1 = pj + c41.z;
            i1 = min(abs(i1), 126 - i1); j1 = min(abs(j1), 126 - j1);
            float v0 = yb[(size_t)c40.x * P + (i0 << 6) + j0];
            float v1 = yb[(size_t)c41.x * P + (i1 << 6) + j1];
            float h0 = fmaxf(fmaf(v0, __int_as_float(c40.w), b0), 0.f);
            float h1 = fmaxf(fmaf(v1, __int_as_float(c41.w), b1), 0.f);
            __nv_bfloat16 hh0 = __float2bfloat16(h0);
            __nv_bfloat16 hh1 = __float2bfloat16(h1);
            __nv_bfloat16 ll0 = __float2bfloat16(h0 - __bfloat162float(hh0));
            __nv_bfloat16 ll1 = __float2bfloat16(h1 - __bfloat162float(hh1));
            uint32_t dst = (uint32_t)(fpx * 128) + (uint32_t)((kloc0 * 2) ^ ((fpx & 7) * 16));
            *(__nv_bfloat162*)(smem + W1_BH + dst) = __nv_bfloat162(hh0, hh1);
            *(__nv_bfloat162*)(smem + W1_BL + dst) = __nv_bfloat162(ll0, ll1);
        }
        __syncthreads();

        const uint32_t abase = (uint32_t)(c * 4096);
#pragma unroll
        for (int ks = 0; ks < 4; ks++) {
            const int colA = ks * 32 + c16A;
            const int colB = ks * 32 + c16B;
            uint32_t ah[2][4], al[2][4];
#pragma unroll
            for (int mf = 0; mf < 2; mf++) {
                uint32_t off = abase + (uint32_t)(rowA[mf] * 128) +
                               (uint32_t)(colA ^ ((rowA[mf] & 7) * 16));
                LDSM4(ah[mf][0], ah[mf][1], ah[mf][2], ah[mf][3], sbase + W1_AH + off);
                LDSM4(al[mf][0], al[mf][1], al[mf][2], al[mf][3], sbase + W1_AL + off);
            }
            uint32_t bh[2][2], bl[2][2];
            {
                uint32_t off = (uint32_t)(rowB * 128) + (uint32_t)(colB ^ ((rowB & 7) * 16));
                LDSM4(bh[0][0], bh[0][1], bh[1][0], bh[1][1], sbase + W1_BH + off);
                LDSM4(bl[0][0], bl[0][1], bl[1][0], bl[1][1], sbase + W1_BL + off);
            }
#pragma unroll
            for (int mf = 0; mf < 2; mf++)
#pragma unroll
                for (int nf = 0; nf < 2; nf++) {
                    MMA_BF16(acc[mf][nf], ah[mf], bh[nf]);
                    MMA_BF16(acc[mf][nf], ah[mf], bl[nf]);
                    MMA_BF16(acc[mf][nf], al[mf], bh[nf]);
                }
        }
        __syncthreads();
    }

    const int r = lid >> 2;
    const int c2 = (lid & 3) * 2;
#pragma unroll
    for (int mf = 0; mf < 2; mf++) {
        int g1 = mf * 16 + r;
        int g2 = g1 + 8;
        float s1 = g_bn2s[g1], sb1 = g_bn2b[g1];
        float s2 = g_bn2s[g2], sb2 = g_bn2b[g2];
#pragma unroll
        for (int nf = 0; nf < 2; nf++) {
            int p = p0 + wid * 16 + nf * 8 + c2;
            float2 v1 = make_float2(fmaxf(fmaf(acc[mf][nf][0], s1, sb1), 0.f),
                                    fmaxf(fmaf(acc[mf][nf][1], s1, sb1), 0.f));
            *(float2*)&g_t[((size_t)b * GG + g1) * P + p] = v1;
            float2 v2 = make_float2(fmaxf(fmaf(acc[mf][nf][2], s2, sb2), 0.f),
                                    fmaxf(fmaf(acc[mf][nf][3], s2, sb2), 0.f));
            *(float2*)&g_t[((size_t)b * GG + g2) * P + p] = v2;
        }
    }
}

// ---------------- K4+K5 fused: per-pixel weight gen + local grouped 3x3 conv ----------------
__global__ __launch_bounds__(256) void wgen2_local_kernel(const float* __restrict__ cw2,
                                                          const float* __restrict__ cb2,
                                                          float* __restrict__ out) {
    __shared__ float ts[GG][64];
    __shared__ float w2s[WOUT * GG];
    __shared__ float cbs[WOUT];
    const int b  = blockIdx.y;
    const int p0 = blockIdx.x * 64;
    const int tid = threadIdx.x;

#pragma unroll
    for (int e = 0; e < 8; e++) {
        int idx = tid + e * 256;
        int g = idx >> 6, n = idx & 63;
        ts[g][n] = g_t[((size_t)b * GG + g) * P + p0 + n];
    }
    for (int idx = tid; idx < WOUT * GG; idx += 256) w2s[idx] = cw2[idx];
    for (int idx = tid; idx < WOUT; idx += 256) cbs[idx] = cb2[idx];
    __syncthreads();

    const int pp = tid & 63;
    const int q  = tid >> 6;
    const int i  = blockIdx.x;
    const int j  = pp;

    float tv[GG];
#pragma unroll
    for (int g = 0; g < GG; g++) tv[g] = ts[g][pp];

#pragma unroll
    for (int g8 = 0; g8 < 8; g8++) {
        const int g = q * 8 + g8;
        float w[9];
#pragma unroll
        for (int t9 = 0; t9 < 9; t9++) {
            float acc = cbs[g * 9 + t9];
            const float4* wrow = (const float4*)&w2s[(g * 9 + t9) * GG];
#pragma unroll
            for (int k4 = 0; k4 < 8; k4++) {
                float4 wv = wrow[k4];
                acc += wv.x * tv[4 * k4] + wv.y * tv[4 * k4 + 1]
                     + wv.z * tv[4 * k4 + 2] + wv.w * tv[4 * k4 + 3];
            }
            w[t9] = acc;
        }
        const float* x3 = g_y + ((size_t)b * MID + 64 + g * SHAREC) * P;
        float* ob = out + ((size_t)b * OUTC + g * SHAREC) * P + p0 + pp;
#pragma unroll
        for (int s = 0; s < SHAREC; s++) {
            const float* xc = x3 + (size_t)s * P;
            float acc = 0.f;
#pragma unroll
            for (int ki = 0; ki < 3; ki++) {
                int ii = i + ki - 1;
                if (ii < 0 || ii > 63) continue;
#pragma unroll
                for (int kj = 0; kj < 3; kj++) {
                    int jj = j + kj - 1;
                    if (jj < 0 || jj > 63) continue;
                    acc += xc[(ii << 6) + jj] * w[ki * 3 + kj];
                }
            }
            ob[(size_t)s * P] = acc;
        }
    }
}

// ---------------- launch ----------------
extern "C" void kernel_launch(void* const* d_in, const int* in_sizes, int n_in,
                              void* d_out, int out_size) {
    const float* x     = (const float*)d_in[0];
    const float* w1    = (const float*)d_in[1];
    const float* b1    = (const float*)d_in[2];
    const float* w2    = (const float*)d_in[3];
    const float* b2    = (const float*)d_in[4];
    const float* w3    = (const float*)d_in[5];
    const float* b3    = (const float*)d_in[6];
    const float* bn1_g = (const float*)d_in[7];
    const float* bn1_b = (const float*)d_in[8];
    const float* bn1_m = (const float*)d_in[9];
    const float* bn1_v = (const float*)d_in[10];
    const float* cw1   = (const float*)d_in[11];
    const float* bn2_g = (const float*)d_in[12];
    const float* bn2_b = (const float*)d_in[13];
    const float* bn2_m = (const float*)d_in[14];
    const float* bn2_v = (const float*)d_in[15];
    const float* cw2   = (const float*)d_in[16];
    const float* cb2   = (const float*)d_in[17];
    float* out = (float*)d_out;

    static int smem_set = 0;
    if (!smem_set) {
        cudaFuncSetAttribute(conv_mma_kernel,
                             cudaFuncAttributeMaxDynamicSharedMemorySize, SM_TOTAL);
        cudaFuncSetAttribute(wgen1_mma_kernel,
                             cudaFuncAttributeMaxDynamicSharedMemorySize, W1_TOTAL);
        smem_set = 1;
    }

    packw_kernel<<<(MIDP * CIN + GG * MID + 255) / 256, 256>>>(w1, w2, w3, cw1);
    packbn_kernel<<<3, 128>>>(b1, b2, b3,
                              bn1_g, bn1_b, bn1_m, bn1_v,
                              bn2_g, bn2_b, bn2_m, bn2_v);
    {
        dim3 grid(P / 32, CIN / 64, BB);      // 128 x 4 x 8
        xconv_kernel<<<grid, 256>>>(x);
    }
    {
        dim3 grid(P / 128, MIDP / 128, BB);   // 32 x 3 x 8
        conv_mma_kernel<<<grid, 256, SM_TOTAL>>>();
    }
    {
        dim3 grid(P / 128, BB);               // 32 x 8
        wgen1_mma_kernel<<<grid, 256, W1_TOTAL>>>();
    }
    {
        dim3 grid(P / 64, BB);                // 64 x 8
        wgen2_local_kernel<<<grid, 256>>>(cw2, cb2, out);
    }
}